// round 11
// baseline (speedup 1.0000x reference)
#include <cuda_runtime.h>
#include <cuda_fp16.h>

#define N_NODES 50000
#define N_EDGES 800000
#define HID 64
#define N_LAYERS 3
#define N_GRAPHS 64
#define NB_NODES 196        // ceil(50000/256)
#define EB4 782             // ceil(800000/4/256)
#define CVB 6250            // N_NODES*32 float2 / 256
#define PERM_SZ (N_EDGES + 3 * N_NODES)
#define N_TASKS 12500       // N_NODES / 4
#define FULL 0xffffffffu
#define WSTRIDE 68          // sWt row stride in floats (16B-aligned, conflict-free)

#define FFMA2(acc, a, b) \
    asm("fma.rn.f32x2 %0, %1, %2, %3;" : "=l"(acc) : "l"(a), "l"(b), "l"(acc))

// ---------------- scratch (device globals; zero-initialized at module load) ----------------
// feature buffers have one extra all-zero row (index N_NODES) used as gather padding;
// no kernel ever writes it, so it stays zero across calls.
__device__ __half g_xh[(N_NODES + 1) * HID];
__device__ __half g_h0[(N_NODES + 1) * HID];
__device__ __half g_h1[(N_NODES + 1) * HID];
__device__ __half g_aggr[N_NODES * HID];   // gathered sums (fp16)
__device__ int    g_deg[N_NODES];        // zero at entry (k_out restores)
__device__ int    g_rowptr[N_NODES];     // padded CSR offsets
__device__ int    g_fill[N_NODES];
__device__ int    g_perm[PERM_SZ];
__device__ float  g_sattr[N_NODES];      // zero at entry (k_out restores)
__device__ float  g_c1[N_LAYERS][HID];
__device__ float  g_c2[N_LAYERS][HID];
__device__ float  g_gsum[N_GRAPHS];      // zeroed in k_scan1
__device__ int    g_ctr[N_LAYERS];       // work-steal counters, zeroed in k_scan1

// ---------------- #1: edge pass 1 (deg + sattr, 4 edges/thread) + fp16 convert ----------------
__global__ void k_pre(const int* __restrict__ ei, const float* __restrict__ ea,
                      const float* __restrict__ x) {
    if (blockIdx.x < EB4) {
        int p = blockIdx.x * 256 + threadIdx.x;
        int e = p * 4;
        if (e >= N_EDGES) return;
        int4   d4 = *(const int4*)  (ei + N_EDGES + e);
        float4 a4 = *(const float4*)(ea + e);
        atomicAdd(&g_deg[d4.x], 1);  atomicAdd(&g_sattr[d4.x], a4.x);
        atomicAdd(&g_deg[d4.y], 1);  atomicAdd(&g_sattr[d4.y], a4.y);
        atomicAdd(&g_deg[d4.z], 1);  atomicAdd(&g_sattr[d4.z], a4.z);
        atomicAdd(&g_deg[d4.w], 1);  atomicAdd(&g_sattr[d4.w], a4.w);
    } else {
        int i = (blockIdx.x - EB4) * 256 + threadIdx.x;   // float2 index
        if (i < N_NODES * 32) {
            float2 v = ((const float2*)x)[i];
            ((__half2*)g_xh)[i] = __floats2half2_rn(v.x, v.y);
        }
    }
}

// ---------------- #2: scan over PADDED degrees + pad-slot fill + constants ----------------
__global__ void __launch_bounds__(256) k_scan1(const float* __restrict__ ew,
                                               const float* __restrict__ eb,
                                               const float* __restrict__ nw) {
    const int b = blockIdx.x, tid = threadIdx.x;
    if (b == NB_NODES) {
        if (tid < N_GRAPHS) g_gsum[tid] = 0.f;
        if (tid < N_LAYERS) g_ctr[tid] = 0;
        if (tid >= N_LAYERS * HID) return;
        int l = tid / HID, h = tid % HID;
        float a = 0.f, c = 0.f;
        for (int k = 0; k < HID; k++) {
            float w = nw[(l * 2 * HID + HID + k) * HID + h];  // W2[k][h]
            a += ew[l * HID + k] * w;
            c += eb[l * HID + k] * w;
        }
        g_c1[l][h] = a;
        g_c2[l][h] = c;
        return;
    }

    __shared__ int sW[8];
    __shared__ int sBase;
    const int lane = tid & 31, w = tid >> 5;

    const int4* __restrict__ d4 = (const int4*)g_deg;
    const int nq = b * 64;
    int s = 0;
    for (int j = tid; j < nq; j += 256) {
        int4 v = d4[j];
        s += ((v.x + 3) & ~3) + ((v.y + 3) & ~3) + ((v.z + 3) & ~3) + ((v.w + 3) & ~3);
    }
#pragma unroll
    for (int o = 16; o; o >>= 1) s += __shfl_down_sync(FULL, s, o);
    if (lane == 0) sW[w] = s;
    __syncthreads();
    if (tid == 0) {
        int t = 0;
#pragma unroll
        for (int j = 0; j < 8; j++) t += sW[j];
        sBase = t;
    }
    __syncthreads();
    const int base = sBase;
    __syncthreads();

    int i = b * 256 + tid;
    int v = (i < N_NODES) ? g_deg[i] : 0;
    int pv = (v + 3) & ~3;
    int inc = pv;
#pragma unroll
    for (int o = 1; o < 32; o <<= 1) {
        int t = __shfl_up_sync(FULL, inc, o);
        if (lane >= o) inc += t;
    }
    if (lane == 31) sW[w] = inc;
    __syncthreads();
    int wo = 0;
    for (int j = 0; j < w; j++) wo += sW[j];
    int exc = base + wo + inc - pv;
    if (i < N_NODES) {
        g_rowptr[i] = exc;
        g_fill[i] = exc;
        for (int t = v; t < pv; t++) g_perm[exc + t] = N_NODES;  // pad -> zero row
    }
}

// ---------------- #3: edge pass 2: CSR bucket placement (4 edges/thread) ----------------
__global__ void k_edge2(const int* __restrict__ ei) {
    int p = blockIdx.x * blockDim.x + threadIdx.x;
    int e = p * 4;
    if (e >= N_EDGES) return;
    int4 s4 = *(const int4*)(ei + e);
    int4 d4 = *(const int4*)(ei + N_EDGES + e);
    g_perm[atomicAdd(&g_fill[d4.x], 1)] = s4.x;
    g_perm[atomicAdd(&g_fill[d4.y], 1)] = s4.y;
    g_perm[atomicAdd(&g_fill[d4.z], 1)] = s4.z;
    g_perm[atomicAdd(&g_fill[d4.w], 1)] = s4.w;
}

// ---------------- gather: zero-smem, quarter-warp owns node, HADD2 accumulate ----------------
__global__ void __launch_bounds__(256, 6) k_gather(const __half* __restrict__ xin, int l) {
    const int lane = threadIdx.x & 31;
    const int q = lane >> 3, c = lane & 7;
    const uint4* __restrict__ xh4 = (const uint4*)xin;

    for (;;) {
        int base;
        if (lane == 0) base = atomicAdd(&g_ctr[l], 4);
        base = __shfl_sync(FULL, base, 0);
        if (base >= N_NODES) break;

        int bp = 0, dp = 0;
        if (lane < 4) {
            bp = g_rowptr[base + lane];
            dp = g_deg[base + lane];
        }
        const int bj = __shfl_sync(FULL, bp, q);
        const int pd = (__shfl_sync(FULL, dp, q) + 3) & ~3;

        __half2 z = __floats2half2_rn(0.f, 0.f);
        __half2 A0[4] = {z, z, z, z};
        __half2 A1[4] = {z, z, z, z};
        __half2 A2[4] = {z, z, z, z};
        __half2 A3[4] = {z, z, z, z};
        const int* __restrict__ pB = g_perm + bj;
        for (int i = 0; i < pd; i += 4) {
            const int s0 = pB[i];
            const int s1 = pB[i + 1];
            const int s2 = pB[i + 2];
            const int s3 = pB[i + 3];
            const uint4 v0 = xh4[s0 * 8 + c];
            const uint4 v1 = xh4[s1 * 8 + c];
            const uint4 v2 = xh4[s2 * 8 + c];
            const uint4 v3 = xh4[s3 * 8 + c];
            A0[0] = __hadd2(A0[0], *(const __half2*)&v0.x);
            A0[1] = __hadd2(A0[1], *(const __half2*)&v0.y);
            A0[2] = __hadd2(A0[2], *(const __half2*)&v0.z);
            A0[3] = __hadd2(A0[3], *(const __half2*)&v0.w);
            A1[0] = __hadd2(A1[0], *(const __half2*)&v1.x);
            A1[1] = __hadd2(A1[1], *(const __half2*)&v1.y);
            A1[2] = __hadd2(A1[2], *(const __half2*)&v1.z);
            A1[3] = __hadd2(A1[3], *(const __half2*)&v1.w);
            A2[0] = __hadd2(A2[0], *(const __half2*)&v2.x);
            A2[1] = __hadd2(A2[1], *(const __half2*)&v2.y);
            A2[2] = __hadd2(A2[2], *(const __half2*)&v2.z);
            A2[3] = __hadd2(A2[3], *(const __half2*)&v2.w);
            A3[0] = __hadd2(A3[0], *(const __half2*)&v3.x);
            A3[1] = __hadd2(A3[1], *(const __half2*)&v3.y);
            A3[2] = __hadd2(A3[2], *(const __half2*)&v3.z);
            A3[3] = __hadd2(A3[3], *(const __half2*)&v3.w);
        }
        // merge 4 slots and store this node's 8 halves per lane (128B/quarter)
        uint4 o;
        __half2 m0 = __hadd2(__hadd2(A0[0], A1[0]), __hadd2(A2[0], A3[0]));
        __half2 m1 = __hadd2(__hadd2(A0[1], A1[1]), __hadd2(A2[1], A3[1]));
        __half2 m2 = __hadd2(__hadd2(A0[2], A1[2]), __hadd2(A2[2], A3[2]));
        __half2 m3 = __hadd2(__hadd2(A0[3], A1[3]), __hadd2(A2[3], A3[3]));
        o.x = *(unsigned*)&m0;  o.y = *(unsigned*)&m1;
        o.z = *(unsigned*)&m2;  o.w = *(unsigned*)&m3;
        ((uint4*)g_aggr)[(base + q) * 8 + c] = o;
    }
}

// ---------------- mlp: dense per-node GEMM + rank-2 edge term + ReLU (+pool) ----------------
__global__ void __launch_bounds__(256, 5) k_mlp(
    __half* __restrict__ xout,
    const float* __restrict__ nw, const float* __restrict__ nb, int l,
    int last, const float* __restrict__ fcw, const int* __restrict__ batch)
{
    __shared__ float sWt[HID * WSTRIDE];   // transposed W1: sWt[h*68+k] = W1[k][h], 17KB
    __shared__ float sA[8][4][HID];        // [warp][node][k]                          8KB
    const int tid = threadIdx.x;

    {
        const float* __restrict__ nwl = nw + (size_t)l * 2 * HID * HID;
        for (int i = tid; i < HID * HID; i += 256) {
            int h = i & 63, k = i >> 6;
            sWt[h * WSTRIDE + k] = nwl[k * HID + h];
        }
    }
    __syncthreads();

    const int warp = tid >> 5, lane = tid & 31;
    const int q = lane >> 3, c = lane & 7;
    const float c1a = g_c1[l][lane], c1b = g_c1[l][lane + 32];
    const float c2a = g_c2[l][lane], c2b = g_c2[l][lane + 32];
    const float ba  = nb[l * HID + lane], bb = nb[l * HID + lane + 32];
    const float fwa = last ? fcw[lane] : 0.f;
    const float fwb = last ? fcw[lane + 32] : 0.f;
    const uint4* __restrict__ ag4 = (const uint4*)g_aggr;

    for (int task = blockIdx.x * 8 + warp; task < N_TASKS; task += gridDim.x * 8) {
        const int base = task * 4;

        // load 4 A rows (quarter q loads node base+q), convert to fp32 in sA
        {
            const uint4 v = ag4[(base + q) * 8 + c];
            float2 f0 = __half22float2(*(const __half2*)&v.x);
            float2 f1 = __half22float2(*(const __half2*)&v.y);
            float2 f2 = __half22float2(*(const __half2*)&v.z);
            float2 f3 = __half22float2(*(const __half2*)&v.w);
            ((float4*)sA[warp][q])[2 * c + 0] = make_float4(f0.x, f0.y, f1.x, f1.y);
            ((float4*)sA[warp][q])[2 * c + 1] = make_float4(f2.x, f2.y, f3.x, f3.y);
        }
        __syncwarp();

        unsigned long long o0p[4] = {0ull, 0ull, 0ull, 0ull};
        unsigned long long o1p[4] = {0ull, 0ull, 0ull, 0ull};
#pragma unroll
        for (int kk = 0; kk < 16; kk++) {
            const ulonglong2 w0 = *(const ulonglong2*)&sWt[lane * WSTRIDE + 4 * kk];
            const ulonglong2 w1 = *(const ulonglong2*)&sWt[(lane + 32) * WSTRIDE + 4 * kk];
#pragma unroll
            for (int j = 0; j < 4; j++) {
                const ulonglong2 av = *(const ulonglong2*)&sA[warp][j][4 * kk]; // broadcast
                FFMA2(o0p[j], av.x, w0.x);
                FFMA2(o0p[j], av.y, w0.y);
                FFMA2(o1p[j], av.x, w1.x);
                FFMA2(o1p[j], av.y, w1.y);
            }
        }
        __syncwarp();

#pragma unroll
        for (int j = 0; j < 4; j++) {
            const int n = base + j;
            float o0lo, o0hi, o1lo, o1hi;
            asm("mov.b64 {%0,%1}, %2;" : "=f"(o0lo), "=f"(o0hi) : "l"(o0p[j]));
            asm("mov.b64 {%0,%1}, %2;" : "=f"(o1lo), "=f"(o1hi) : "l"(o1p[j]));
            const float sa = g_sattr[n];
            const float dg = (float)g_deg[n];
            float u0 = (o0lo + o0hi) + sa * c1a + dg * c2a + ba;
            float u1 = (o1lo + o1hi) + sa * c1b + dg * c2b + bb;
            u0 = fmaxf(u0, 0.f);   // ReLU; LeakyReLU identity on >= 0
            u1 = fmaxf(u1, 0.f);
            if (!last) {
                xout[n * HID + lane]      = __float2half_rn(u0);
                xout[n * HID + lane + 32] = __float2half_rn(u1);
            } else {
                float s = u0 * fwa + u1 * fwb;
#pragma unroll
                for (int off = 16; off; off >>= 1) s += __shfl_down_sync(FULL, s, off);
                if (lane == 0) atomicAdd(&g_gsum[batch[n]], s);
            }
        }
    }
}

// ---------------- final output (block 0) + scratch cleanup (blocks 1..) ----------------
__global__ void k_out(float* __restrict__ out, const float* __restrict__ fcb,
                      const int* __restrict__ batch) {
    if (blockIdx.x == 0) {
        int g = threadIdx.x;
        if (g >= N_GRAPHS) return;
        int lo = 0, hi = N_NODES;
        while (lo < hi) { int m = (lo + hi) >> 1; if (batch[m] < g) lo = m + 1; else hi = m; }
        int lo2 = lo, hi2 = N_NODES;
        while (lo2 < hi2) { int m = (lo2 + hi2) >> 1; if (batch[m] < g + 1) lo2 = m + 1; else hi2 = m; }
        float c = (float)(lo2 - lo);
        out[g] = g_gsum[g] / fmaxf(c, 1.f) + fcb[0];
    } else {
        int i = (blockIdx.x - 1) * 256 + threadIdx.x;
        if (i < N_NODES) { g_deg[i] = 0; g_sattr[i] = 0.f; }
    }
}

// ---------------- launch ----------------
extern "C" void kernel_launch(void* const* d_in, const int* in_sizes, int n_in,
                              void* d_out, int out_size) {
    const float* x    = (const float*)d_in[0];
    const float* ea   = (const float*)d_in[1];
    const float* ew   = (const float*)d_in[2];
    const float* eb   = (const float*)d_in[3];
    const float* nw   = (const float*)d_in[4];
    const float* nb   = (const float*)d_in[5];
    const float* fcw  = (const float*)d_in[6];
    const float* fcb  = (const float*)d_in[7];
    const int*   ei   = (const int*)d_in[8];
    const int*   batch= (const int*)d_in[9];
    float* out = (float*)d_out;

    __half* xh; cudaGetSymbolAddress((void**)&xh, g_xh);
    __half* h0; cudaGetSymbolAddress((void**)&h0, g_h0);
    __half* h1; cudaGetSymbolAddress((void**)&h1, g_h1);

    k_pre   <<<EB4 + CVB, 256>>>(ei, ea, x);        // #1
    k_scan1 <<<NB_NODES + 1, 256>>>(ew, eb, nw);    // #2
    k_edge2 <<<EB4, 256>>>(ei);                     // #3

    const int GB = 888;    // 6 blocks/SM, zero smem, work-stealing
    const int MB = 740;    // 5 blocks/SM

    k_gather<<<GB, 256>>>(xh, 0);                             // #4 -> profiled
    k_mlp   <<<MB, 256>>>(h0, nw, nb, 0, 0, fcw, batch);      // #5
    k_gather<<<GB, 256>>>(h0, 1);                             // #6
    k_mlp   <<<MB, 256>>>(h1, nw, nb, 1, 0, fcw, batch);      // #7
    k_gather<<<GB, 256>>>(h1, 2);                             // #8
    k_mlp   <<<MB, 256>>>(h0, nw, nb, 2, 1, fcw, batch);      // #9 fused pooling

    k_out<<<NB_NODES + 1, 256>>>(out, fcb, batch);            // #10
}

// round 12
// speedup vs baseline: 1.0986x; 1.0986x over previous
#include <cuda_runtime.h>
#include <cuda_fp16.h>

#define N_NODES 50000
#define N_EDGES 800000
#define HID 64
#define N_LAYERS 3
#define N_GRAPHS 64
#define NB_NODES 196        // ceil(50000/256)
#define EB4 782             // ceil(800000/4/256)
#define CVB 6250            // N_NODES*32 float2 / 256
#define PERM_SZ (N_EDGES + 3 * N_NODES)
#define FULL 0xffffffffu
#define WSTRIDE 68          // sWt row stride in floats (16B-aligned, conflict-free)

#define FFMA2(acc, a, b) \
    asm("fma.rn.f32x2 %0, %1, %2, %3;" : "=l"(acc) : "l"(a), "l"(b), "l"(acc))

// ---------------- scratch (device globals; zero-initialized at module load) ----------------
// feature buffers have one extra all-zero row (index N_NODES) used as gather padding;
// no kernel ever writes it, so it stays zero across calls.
__device__ __half g_xh[(N_NODES + 1) * HID];
__device__ __half g_h0[(N_NODES + 1) * HID];
__device__ __half g_h1[(N_NODES + 1) * HID];
__device__ int    g_deg[N_NODES];        // zero at entry (k_out restores)
__device__ int    g_rowptr[N_NODES];     // padded CSR offsets (multiples of 4)
__device__ int    g_fill[N_NODES];
__device__ __align__(16) int g_perm[PERM_SZ];
__device__ float  g_sattr[N_NODES];      // zero at entry (k_out restores)
__device__ float  g_c1[N_LAYERS][HID];
__device__ float  g_c2[N_LAYERS][HID];
__device__ float  g_gsum[N_GRAPHS];      // zeroed in k_scan1
__device__ int    g_ctr[N_LAYERS];       // work-steal counters, zeroed in k_scan1

// ---------------- #1: edge pass 1 (deg + sattr, 4 edges/thread) + fp16 convert ----------------
__global__ void k_pre(const int* __restrict__ ei, const float* __restrict__ ea,
                      const float* __restrict__ x) {
    if (blockIdx.x < EB4) {
        int p = blockIdx.x * 256 + threadIdx.x;
        int e = p * 4;
        if (e >= N_EDGES) return;
        int4   d4 = *(const int4*)  (ei + N_EDGES + e);
        float4 a4 = *(const float4*)(ea + e);
        atomicAdd(&g_deg[d4.x], 1);  atomicAdd(&g_sattr[d4.x], a4.x);
        atomicAdd(&g_deg[d4.y], 1);  atomicAdd(&g_sattr[d4.y], a4.y);
        atomicAdd(&g_deg[d4.z], 1);  atomicAdd(&g_sattr[d4.z], a4.z);
        atomicAdd(&g_deg[d4.w], 1);  atomicAdd(&g_sattr[d4.w], a4.w);
    } else {
        int i = (blockIdx.x - EB4) * 256 + threadIdx.x;   // float2 index
        if (i < N_NODES * 32) {
            float2 v = ((const float2*)x)[i];
            ((__half2*)g_xh)[i] = __floats2half2_rn(v.x, v.y);
        }
    }
}

// ---------------- #2: scan over PADDED degrees + pad-slot fill + constants ----------------
__global__ void __launch_bounds__(256) k_scan1(const float* __restrict__ ew,
                                               const float* __restrict__ eb,
                                               const float* __restrict__ nw) {
    const int b = blockIdx.x, tid = threadIdx.x;
    if (b == NB_NODES) {
        if (tid < N_GRAPHS) g_gsum[tid] = 0.f;
        if (tid < N_LAYERS) g_ctr[tid] = 0;
        if (tid >= N_LAYERS * HID) return;
        int l = tid / HID, h = tid % HID;
        float a = 0.f, c = 0.f;
        for (int k = 0; k < HID; k++) {
            float w = nw[(l * 2 * HID + HID + k) * HID + h];  // W2[k][h]
            a += ew[l * HID + k] * w;
            c += eb[l * HID + k] * w;
        }
        g_c1[l][h] = a;
        g_c2[l][h] = c;
        return;
    }

    __shared__ int sW[8];
    __shared__ int sBase;
    const int lane = tid & 31, w = tid >> 5;

    const int4* __restrict__ d4 = (const int4*)g_deg;
    const int nq = b * 64;
    int s = 0;
    for (int j = tid; j < nq; j += 256) {
        int4 v = d4[j];
        s += ((v.x + 3) & ~3) + ((v.y + 3) & ~3) + ((v.z + 3) & ~3) + ((v.w + 3) & ~3);
    }
#pragma unroll
    for (int o = 16; o; o >>= 1) s += __shfl_down_sync(FULL, s, o);
    if (lane == 0) sW[w] = s;
    __syncthreads();
    if (tid == 0) {
        int t = 0;
#pragma unroll
        for (int j = 0; j < 8; j++) t += sW[j];
        sBase = t;
    }
    __syncthreads();
    const int base = sBase;
    __syncthreads();

    int i = b * 256 + tid;
    int v = (i < N_NODES) ? g_deg[i] : 0;
    int pv = (v + 3) & ~3;
    int inc = pv;
#pragma unroll
    for (int o = 1; o < 32; o <<= 1) {
        int t = __shfl_up_sync(FULL, inc, o);
        if (lane >= o) inc += t;
    }
    if (lane == 31) sW[w] = inc;
    __syncthreads();
    int wo = 0;
    for (int j = 0; j < w; j++) wo += sW[j];
    int exc = base + wo + inc - pv;
    if (i < N_NODES) {
        g_rowptr[i] = exc;
        g_fill[i] = exc;
        for (int t = v; t < pv; t++) g_perm[exc + t] = N_NODES;  // pad -> zero row
    }
}

// ---------------- #3: edge pass 2: CSR bucket placement (4 edges/thread) ----------------
__global__ void k_edge2(const int* __restrict__ ei) {
    int p = blockIdx.x * blockDim.x + threadIdx.x;
    int e = p * 4;
    if (e >= N_EDGES) return;
    int4 s4 = *(const int4*)(ei + e);
    int4 d4 = *(const int4*)(ei + N_EDGES + e);
    g_perm[atomicAdd(&g_fill[d4.x], 1)] = s4.x;
    g_perm[atomicAdd(&g_fill[d4.y], 1)] = s4.y;
    g_perm[atomicAdd(&g_fill[d4.z], 1)] = s4.z;
    g_perm[atomicAdd(&g_fill[d4.w], 1)] = s4.w;
}

// ---------------- #4-6: fused layer: int4-perm HADD2 gather + f32x2 MLP, 6 blk/SM ----------------
__global__ void __launch_bounds__(256, 6) k_layer(
    const __half* __restrict__ xin, __half* __restrict__ xout,
    const float* __restrict__ nw, const float* __restrict__ nb, int l,
    int last, const float* __restrict__ fcw, const int* __restrict__ batch)
{
    __shared__ float sWt[HID * WSTRIDE];   // transposed W1: sWt[h*68+k] = W1[k][h], 17KB
    __shared__ float sA[8][4][HID];        // [warp][node][k]                          8KB
    const int tid = threadIdx.x;

    {
        const float* __restrict__ nwl = nw + (size_t)l * 2 * HID * HID;
        for (int i = tid; i < HID * HID; i += 256) {
            int h = i & 63, k = i >> 6;
            sWt[h * WSTRIDE + k] = nwl[k * HID + h];
        }
    }
    __syncthreads();

    const int warp = tid >> 5, lane = tid & 31;
    const int q = lane >> 3, c = lane & 7;   // quarter-warp id (= owned node), col-block
    const float c1a = g_c1[l][lane], c1b = g_c1[l][lane + 32];
    const float c2a = g_c2[l][lane], c2b = g_c2[l][lane + 32];
    const float ba  = nb[l * HID + lane], bb = nb[l * HID + lane + 32];
    const float fwa = last ? fcw[lane] : 0.f;
    const float fwb = last ? fcw[lane + 32] : 0.f;
    const uint4* __restrict__ xh4 = (const uint4*)xin;   // 8 halves per lane

    for (;;) {
        int base;
        if (lane == 0) base = atomicAdd(&g_ctr[l], 4);
        base = __shfl_sync(FULL, base, 0);
        if (base >= N_NODES) break;

        int bp = 0, dp = 0;
        if (lane < 4 && base + lane < N_NODES) {
            bp = g_rowptr[base + lane];
            dp = g_deg[base + lane];
        }
        const int bj = __shfl_sync(FULL, bp, q);   // this quarter's padded CSR start
        const int cj = __shfl_sync(FULL, dp, q);   // real degree
        const int pd = (cj + 3) & ~3;              // padded degree (multiple of 4)

        // ---- gather: flat loop, int4 perm load, fp16x2 accumulation ----
        __half2 z = __floats2half2_rn(0.f, 0.f);
        __half2 A0[4] = {z, z, z, z};
        __half2 A1[4] = {z, z, z, z};
        __half2 A2[4] = {z, z, z, z};
        __half2 A3[4] = {z, z, z, z};
        {
            const int4* __restrict__ pB4 = (const int4*)(g_perm + bj);  // 16B aligned
#pragma unroll 2
            for (int i = 0; i < (pd >> 2); i++) {
                const int4 s4 = pB4[i];                 // one LDG.128: 4 indices
                const uint4 v0 = xh4[s4.x * 8 + c];
                const uint4 v1 = xh4[s4.y * 8 + c];
                const uint4 v2 = xh4[s4.z * 8 + c];
                const uint4 v3 = xh4[s4.w * 8 + c];
                A0[0] = __hadd2(A0[0], *(const __half2*)&v0.x);
                A0[1] = __hadd2(A0[1], *(const __half2*)&v0.y);
                A0[2] = __hadd2(A0[2], *(const __half2*)&v0.z);
                A0[3] = __hadd2(A0[3], *(const __half2*)&v0.w);
                A1[0] = __hadd2(A1[0], *(const __half2*)&v1.x);
                A1[1] = __hadd2(A1[1], *(const __half2*)&v1.y);
                A1[2] = __hadd2(A1[2], *(const __half2*)&v1.z);
                A1[3] = __hadd2(A1[3], *(const __half2*)&v1.w);
                A2[0] = __hadd2(A2[0], *(const __half2*)&v2.x);
                A2[1] = __hadd2(A2[1], *(const __half2*)&v2.y);
                A2[2] = __hadd2(A2[2], *(const __half2*)&v2.z);
                A2[3] = __hadd2(A2[3], *(const __half2*)&v2.w);
                A3[0] = __hadd2(A3[0], *(const __half2*)&v3.x);
                A3[1] = __hadd2(A3[1], *(const __half2*)&v3.y);
                A3[2] = __hadd2(A3[2], *(const __half2*)&v3.z);
                A3[3] = __hadd2(A3[3], *(const __half2*)&v3.w);
            }
        }
        // merge 4 row-slots, convert to fp32, store to sA (quarter owns its node)
        {
            __half2 m0 = __hadd2(__hadd2(A0[0], A1[0]), __hadd2(A2[0], A3[0]));
            __half2 m1 = __hadd2(__hadd2(A0[1], A1[1]), __hadd2(A2[1], A3[1]));
            __half2 m2 = __hadd2(__hadd2(A0[2], A1[2]), __hadd2(A2[2], A3[2]));
            __half2 m3 = __hadd2(__hadd2(A0[3], A1[3]), __hadd2(A2[3], A3[3]));
            float2 f0 = __half22float2(m0);
            float2 f1 = __half22float2(m1);
            float2 f2 = __half22float2(m2);
            float2 f3 = __half22float2(m3);
            ((float4*)sA[warp][q])[2 * c + 0] = make_float4(f0.x, f0.y, f1.x, f1.y);
            ((float4*)sA[warp][q])[2 * c + 1] = make_float4(f2.x, f2.y, f3.x, f3.y);
        }
        __syncwarp();

        // ---- MLP: packed f32x2 FMA along k; weights reused across 4 nodes ----
        unsigned long long o0p[4] = {0ull, 0ull, 0ull, 0ull};
        unsigned long long o1p[4] = {0ull, 0ull, 0ull, 0ull};
#pragma unroll
        for (int kk = 0; kk < 16; kk++) {
            const ulonglong2 w0 = *(const ulonglong2*)&sWt[lane * WSTRIDE + 4 * kk];
            const ulonglong2 w1 = *(const ulonglong2*)&sWt[(lane + 32) * WSTRIDE + 4 * kk];
#pragma unroll
            for (int j = 0; j < 4; j++) {
                const ulonglong2 av = *(const ulonglong2*)&sA[warp][j][4 * kk]; // broadcast
                FFMA2(o0p[j], av.x, w0.x);
                FFMA2(o0p[j], av.y, w0.y);
                FFMA2(o1p[j], av.x, w1.x);
                FFMA2(o1p[j], av.y, w1.y);
            }
        }
        __syncwarp();

        // ---- epilogue: horizontal add + rank-2 edge term + bias + ReLU ----
#pragma unroll
        for (int j = 0; j < 4; j++) {
            const int n = base + j;
            if (n >= N_NODES) break;
            float o0lo, o0hi, o1lo, o1hi;
            asm("mov.b64 {%0,%1}, %2;" : "=f"(o0lo), "=f"(o0hi) : "l"(o0p[j]));
            asm("mov.b64 {%0,%1}, %2;" : "=f"(o1lo), "=f"(o1hi) : "l"(o1p[j]));
            const float sa = g_sattr[n];
            const float dg = (float)__shfl_sync(FULL, dp, j);
            float u0 = (o0lo + o0hi) + sa * c1a + dg * c2a + ba;
            float u1 = (o1lo + o1hi) + sa * c1b + dg * c2b + bb;
            u0 = fmaxf(u0, 0.f);   // ReLU; LeakyReLU identity on >= 0
            u1 = fmaxf(u1, 0.f);
            if (!last) {
                xout[n * HID + lane]      = __float2half_rn(u0);
                xout[n * HID + lane + 32] = __float2half_rn(u1);
            } else {
                float s = u0 * fwa + u1 * fwb;
#pragma unroll
                for (int off = 16; off; off >>= 1) s += __shfl_down_sync(FULL, s, off);
                if (lane == 0) atomicAdd(&g_gsum[batch[n]], s);
            }
        }
    }
}

// ---------------- #7: final output (block 0) + scratch cleanup (blocks 1..) ----------------
__global__ void k_out(float* __restrict__ out, const float* __restrict__ fcb,
                      const int* __restrict__ batch) {
    if (blockIdx.x == 0) {
        int g = threadIdx.x;
        if (g >= N_GRAPHS) return;
        int lo = 0, hi = N_NODES;
        while (lo < hi) { int m = (lo + hi) >> 1; if (batch[m] < g) lo = m + 1; else hi = m; }
        int lo2 = lo, hi2 = N_NODES;
        while (lo2 < hi2) { int m = (lo2 + hi2) >> 1; if (batch[m] < g + 1) lo2 = m + 1; else hi2 = m; }
        float c = (float)(lo2 - lo);
        out[g] = g_gsum[g] / fmaxf(c, 1.f) + fcb[0];
    } else {
        int i = (blockIdx.x - 1) * 256 + threadIdx.x;
        if (i < N_NODES) { g_deg[i] = 0; g_sattr[i] = 0.f; }
    }
}

// ---------------- launch ----------------
extern "C" void kernel_launch(void* const* d_in, const int* in_sizes, int n_in,
                              void* d_out, int out_size) {
    const float* x    = (const float*)d_in[0];
    const float* ea   = (const float*)d_in[1];
    const float* ew   = (const float*)d_in[2];
    const float* eb   = (const float*)d_in[3];
    const float* nw   = (const float*)d_in[4];
    const float* nb   = (const float*)d_in[5];
    const float* fcw  = (const float*)d_in[6];
    const float* fcb  = (const float*)d_in[7];
    const int*   ei   = (const int*)d_in[8];
    const int*   batch= (const int*)d_in[9];
    float* out = (float*)d_out;

    __half* xh; cudaGetSymbolAddress((void**)&xh, g_xh);
    __half* h0; cudaGetSymbolAddress((void**)&h0, g_h0);
    __half* h1; cudaGetSymbolAddress((void**)&h1, g_h1);

    k_pre  <<<EB4 + CVB, 256>>>(ei, ea, x);        // #1
    k_scan1<<<NB_NODES + 1, 256>>>(ew, eb, nw);    // #2
    k_edge2<<<EB4, 256>>>(ei);                     // #3

    const int LB = 888;                            // 6 blocks/SM, work-stealing
    k_layer<<<LB, 256>>>(xh, h0, nw, nb, 0, 0, fcw, batch);   // #4 -> profiled
    k_layer<<<LB, 256>>>(h0, h1, nw, nb, 1, 0, fcw, batch);   // #5
    k_layer<<<LB, 256>>>(h1, h0, nw, nb, 2, 1, fcw, batch);   // #6 fused pooling

    k_out<<<NB_NODES + 1, 256>>>(out, fcb, batch); // #7 output + cleanup
}

// round 13
// speedup vs baseline: 1.2164x; 1.1072x over previous
#include <cuda_runtime.h>
#include <cuda_fp16.h>

#define N_NODES 50000
#define N_EDGES 800000
#define HID 64
#define N_LAYERS 3
#define N_GRAPHS 64
#define NB_NODES 196        // ceil(50000/256)
#define EB4 782             // ceil(800000/4/256)
#define CVB 6250            // N_NODES*32 float2 / 256
#define PERM_SZ (N_EDGES + 3 * N_NODES)
#define FULL 0xffffffffu
#define WH_STRIDE 33        // sWh row stride in half2 (conflict-free)

#define FFMA2(acc, a, b) \
    asm("fma.rn.f32x2 %0, %1, %2, %3;" : "=l"(acc) : "l"(a), "l"(b), "l"(acc))

// ---------------- scratch (device globals; zero-initialized at module load) ----------------
// feature buffers have one extra all-zero row (index N_NODES) used as gather padding.
__device__ __half g_xh[(N_NODES + 1) * HID];
__device__ __half g_h0[(N_NODES + 1) * HID];
__device__ __half g_h1[(N_NODES + 1) * HID];
__device__ int    g_deg[N_NODES];        // zero at entry (k_out restores)
__device__ int    g_rowptr[N_NODES];     // padded CSR offsets (multiples of 4)
__device__ int    g_fill[N_NODES];
__device__ __align__(16) int g_perm[PERM_SZ];
__device__ float  g_sattr[N_NODES];      // zero at entry (k_out restores)
__device__ float  g_c1[N_LAYERS][HID];
__device__ float  g_c2[N_LAYERS][HID];
__device__ float  g_gsum[N_GRAPHS];      // zeroed in k_scan1
__device__ int    g_ctr[N_LAYERS];       // work-steal counters, zeroed in k_scan1

// ---------------- #1: edge pass 1 (deg + sattr, 4 edges/thread) + fp16 convert ----------------
__global__ void k_pre(const int* __restrict__ ei, const float* __restrict__ ea,
                      const float* __restrict__ x) {
    if (blockIdx.x < EB4) {
        int p = blockIdx.x * 256 + threadIdx.x;
        int e = p * 4;
        if (e >= N_EDGES) return;
        int4   d4 = *(const int4*)  (ei + N_EDGES + e);
        float4 a4 = *(const float4*)(ea + e);
        atomicAdd(&g_deg[d4.x], 1);  atomicAdd(&g_sattr[d4.x], a4.x);
        atomicAdd(&g_deg[d4.y], 1);  atomicAdd(&g_sattr[d4.y], a4.y);
        atomicAdd(&g_deg[d4.z], 1);  atomicAdd(&g_sattr[d4.z], a4.z);
        atomicAdd(&g_deg[d4.w], 1);  atomicAdd(&g_sattr[d4.w], a4.w);
    } else {
        int i = (blockIdx.x - EB4) * 256 + threadIdx.x;   // float2 index
        if (i < N_NODES * 32) {
            float2 v = ((const float2*)x)[i];
            ((__half2*)g_xh)[i] = __floats2half2_rn(v.x, v.y);
        }
    }
}

// ---------------- #2: scan over PADDED degrees + pad-slot fill + constants ----------------
__global__ void __launch_bounds__(256) k_scan1(const float* __restrict__ ew,
                                               const float* __restrict__ eb,
                                               const float* __restrict__ nw) {
    const int b = blockIdx.x, tid = threadIdx.x;
    if (b == NB_NODES) {
        if (tid < N_GRAPHS) g_gsum[tid] = 0.f;
        if (tid < N_LAYERS) g_ctr[tid] = 0;
        if (tid >= N_LAYERS * HID) return;
        int l = tid / HID, h = tid % HID;
        float a = 0.f, c = 0.f;
        for (int k = 0; k < HID; k++) {
            float w = nw[(l * 2 * HID + HID + k) * HID + h];  // W2[k][h]
            a += ew[l * HID + k] * w;
            c += eb[l * HID + k] * w;
        }
        g_c1[l][h] = a;
        g_c2[l][h] = c;
        return;
    }

    __shared__ int sW[8];
    __shared__ int sBase;
    const int lane = tid & 31, w = tid >> 5;

    const int4* __restrict__ d4 = (const int4*)g_deg;
    const int nq = b * 64;
    int s = 0;
    for (int j = tid; j < nq; j += 256) {
        int4 v = d4[j];
        s += ((v.x + 3) & ~3) + ((v.y + 3) & ~3) + ((v.z + 3) & ~3) + ((v.w + 3) & ~3);
    }
#pragma unroll
    for (int o = 16; o; o >>= 1) s += __shfl_down_sync(FULL, s, o);
    if (lane == 0) sW[w] = s;
    __syncthreads();
    if (tid == 0) {
        int t = 0;
#pragma unroll
        for (int j = 0; j < 8; j++) t += sW[j];
        sBase = t;
    }
    __syncthreads();
    const int base = sBase;
    __syncthreads();

    int i = b * 256 + tid;
    int v = (i < N_NODES) ? g_deg[i] : 0;
    int pv = (v + 3) & ~3;
    int inc = pv;
#pragma unroll
    for (int o = 1; o < 32; o <<= 1) {
        int t = __shfl_up_sync(FULL, inc, o);
        if (lane >= o) inc += t;
    }
    if (lane == 31) sW[w] = inc;
    __syncthreads();
    int wo = 0;
    for (int j = 0; j < w; j++) wo += sW[j];
    int exc = base + wo + inc - pv;
    if (i < N_NODES) {
        g_rowptr[i] = exc;
        g_fill[i] = exc;
        for (int t = v; t < pv; t++) g_perm[exc + t] = N_NODES;  // pad -> zero row
    }
}

// ---------------- #3: edge pass 2: CSR bucket placement (4 edges/thread) ----------------
__global__ void k_edge2(const int* __restrict__ ei) {
    int p = blockIdx.x * blockDim.x + threadIdx.x;
    int e = p * 4;
    if (e >= N_EDGES) return;
    int4 s4 = *(const int4*)(ei + e);
    int4 d4 = *(const int4*)(ei + N_EDGES + e);
    g_perm[atomicAdd(&g_fill[d4.x], 1)] = s4.x;
    g_perm[atomicAdd(&g_fill[d4.y], 1)] = s4.y;
    g_perm[atomicAdd(&g_fill[d4.z], 1)] = s4.z;
    g_perm[atomicAdd(&g_fill[d4.w], 1)] = s4.w;
}

// ---------------- #4-6: fused layer: 8 nodes/task, fp16-weight MLP ----------------
__global__ void __launch_bounds__(256, 4) k_layer(
    const __half* __restrict__ xin, __half* __restrict__ xout,
    const float* __restrict__ nw, const float* __restrict__ nb, int l,
    int last, const float* __restrict__ fcw, const int* __restrict__ batch)
{
    __shared__ __half2 sWh[HID * WH_STRIDE];  // sWh[h*33+kp] = (W[2kp][h], W[2kp+1][h]) 8.4KB
    __shared__ float   sA[8][8][HID];         // [warp][node][k]                        16KB
    const int tid = threadIdx.x;

    // stage W1 as half2 pairs along k, transposed (h-major)
    {
        const float* __restrict__ nwl = nw + (size_t)l * 2 * HID * HID;
        for (int i = tid; i < HID * 32; i += 256) {
            int h = i & 63, kp = i >> 6;
            float w0 = nwl[(2 * kp) * HID + h];
            float w1 = nwl[(2 * kp + 1) * HID + h];
            sWh[h * WH_STRIDE + kp] = __floats2half2_rn(w0, w1);
        }
    }
    __syncthreads();

    const int warp = tid >> 5, lane = tid & 31;
    const int q = lane >> 3, c = lane & 7;   // quarter-warp id, col-block
    const float c1a = g_c1[l][lane], c1b = g_c1[l][lane + 32];
    const float c2a = g_c2[l][lane], c2b = g_c2[l][lane + 32];
    const float ba  = nb[l * HID + lane], bb = nb[l * HID + lane + 32];
    const float fwa = last ? fcw[lane] : 0.f;
    const float fwb = last ? fcw[lane + 32] : 0.f;
    const uint4* __restrict__ xh4 = (const uint4*)xin;   // 8 halves per lane

    for (;;) {
        int base;
        if (lane == 0) base = atomicAdd(&g_ctr[l], 8);
        base = __shfl_sync(FULL, base, 0);
        if (base >= N_NODES) break;

        int bp = 0, dp = 0;
        if (lane < 8) {
            bp = g_rowptr[base + lane];
            dp = g_deg[base + lane];
        }

        // ---- gather: each quarter-warp owns nodes base+q and base+q+4 ----
#pragma unroll
        for (int half = 0; half < 2; half++) {
            const int slot = q + 4 * half;
            const int bj = __shfl_sync(FULL, bp, slot);
            const int pd = (__shfl_sync(FULL, dp, slot) + 3) & ~3;

            __half2 z = __floats2half2_rn(0.f, 0.f);
            __half2 A0[4] = {z, z, z, z};
            __half2 A1[4] = {z, z, z, z};
            __half2 A2[4] = {z, z, z, z};
            __half2 A3[4] = {z, z, z, z};
            const int4* __restrict__ pB4 = (const int4*)(g_perm + bj);  // 16B aligned
#pragma unroll 2
            for (int i = 0; i < (pd >> 2); i++) {
                const int4 s4 = pB4[i];                 // one LDG.128: 4 indices
                const uint4 v0 = xh4[s4.x * 8 + c];
                const uint4 v1 = xh4[s4.y * 8 + c];
                const uint4 v2 = xh4[s4.z * 8 + c];
                const uint4 v3 = xh4[s4.w * 8 + c];
                A0[0] = __hadd2(A0[0], *(const __half2*)&v0.x);
                A0[1] = __hadd2(A0[1], *(const __half2*)&v0.y);
                A0[2] = __hadd2(A0[2], *(const __half2*)&v0.z);
                A0[3] = __hadd2(A0[3], *(const __half2*)&v0.w);
                A1[0] = __hadd2(A1[0], *(const __half2*)&v1.x);
                A1[1] = __hadd2(A1[1], *(const __half2*)&v1.y);
                A1[2] = __hadd2(A1[2], *(const __half2*)&v1.z);
                A1[3] = __hadd2(A1[3], *(const __half2*)&v1.w);
                A2[0] = __hadd2(A2[0], *(const __half2*)&v2.x);
                A2[1] = __hadd2(A2[1], *(const __half2*)&v2.y);
                A2[2] = __hadd2(A2[2], *(const __half2*)&v2.z);
                A2[3] = __hadd2(A2[3], *(const __half2*)&v2.w);
                A3[0] = __hadd2(A3[0], *(const __half2*)&v3.x);
                A3[1] = __hadd2(A3[1], *(const __half2*)&v3.y);
                A3[2] = __hadd2(A3[2], *(const __half2*)&v3.z);
                A3[3] = __hadd2(A3[3], *(const __half2*)&v3.w);
            }
            __half2 m0 = __hadd2(__hadd2(A0[0], A1[0]), __hadd2(A2[0], A3[0]));
            __half2 m1 = __hadd2(__hadd2(A0[1], A1[1]), __hadd2(A2[1], A3[1]));
            __half2 m2 = __hadd2(__hadd2(A0[2], A1[2]), __hadd2(A2[2], A3[2]));
            __half2 m3 = __hadd2(__hadd2(A0[3], A1[3]), __hadd2(A2[3], A3[3]));
            float2 f0 = __half22float2(m0);
            float2 f1 = __half22float2(m1);
            float2 f2 = __half22float2(m2);
            float2 f3 = __half22float2(m3);
            ((float4*)sA[warp][slot])[2 * c + 0] = make_float4(f0.x, f0.y, f1.x, f1.y);
            ((float4*)sA[warp][slot])[2 * c + 1] = make_float4(f2.x, f2.y, f3.x, f3.y);
        }
        __syncwarp();

        // ---- MLP: fp16 weights (LDS.64), f32x2 FMA, reused across 8 nodes ----
        unsigned long long o0p[8] = {0,0,0,0,0,0,0,0};
        unsigned long long o1p[8] = {0,0,0,0,0,0,0,0};
#pragma unroll
        for (int kk = 0; kk < 16; kk++) {
            // 4 k-values per step: 2 half2 per h-column
            const __half2 wa0 = sWh[lane * WH_STRIDE + 2 * kk];
            const __half2 wa1 = sWh[lane * WH_STRIDE + 2 * kk + 1];
            const __half2 wb0 = sWh[(lane + 32) * WH_STRIDE + 2 * kk];
            const __half2 wb1 = sWh[(lane + 32) * WH_STRIDE + 2 * kk + 1];
            float2 fa0 = __half22float2(wa0), fa1 = __half22float2(wa1);
            float2 fb0 = __half22float2(wb0), fb1 = __half22float2(wb1);
            unsigned long long pa0, pa1, pb0, pb1;
            asm("mov.b64 %0, {%1,%2};" : "=l"(pa0) : "f"(fa0.x), "f"(fa0.y));
            asm("mov.b64 %0, {%1,%2};" : "=l"(pa1) : "f"(fa1.x), "f"(fa1.y));
            asm("mov.b64 %0, {%1,%2};" : "=l"(pb0) : "f"(fb0.x), "f"(fb0.y));
            asm("mov.b64 %0, {%1,%2};" : "=l"(pb1) : "f"(fb1.x), "f"(fb1.y));
#pragma unroll
            for (int j = 0; j < 8; j++) {
                const ulonglong2 av = *(const ulonglong2*)&sA[warp][j][4 * kk]; // broadcast
                FFMA2(o0p[j], av.x, pa0);
                FFMA2(o0p[j], av.y, pa1);
                FFMA2(o1p[j], av.x, pb0);
                FFMA2(o1p[j], av.y, pb1);
            }
        }
        __syncwarp();

        // ---- epilogue: horizontal add + rank-2 edge term + bias + ReLU ----
#pragma unroll
        for (int j = 0; j < 8; j++) {
            const int n = base + j;
            if (n >= N_NODES) break;
            float o0lo, o0hi, o1lo, o1hi;
            asm("mov.b64 {%0,%1}, %2;" : "=f"(o0lo), "=f"(o0hi) : "l"(o0p[j]));
            asm("mov.b64 {%0,%1}, %2;" : "=f"(o1lo), "=f"(o1hi) : "l"(o1p[j]));
            const float sa = g_sattr[n];
            const float dg = (float)__shfl_sync(FULL, dp, j);
            float u0 = (o0lo + o0hi) + sa * c1a + dg * c2a + ba;
            float u1 = (o1lo + o1hi) + sa * c1b + dg * c2b + bb;
            u0 = fmaxf(u0, 0.f);   // ReLU; LeakyReLU identity on >= 0
            u1 = fmaxf(u1, 0.f);
            if (!last) {
                xout[n * HID + lane]      = __float2half_rn(u0);
                xout[n * HID + lane + 32] = __float2half_rn(u1);
            } else {
                float s = u0 * fwa + u1 * fwb;
#pragma unroll
                for (int off = 16; off; off >>= 1) s += __shfl_down_sync(FULL, s, off);
                if (lane == 0) atomicAdd(&g_gsum[batch[n]], s);
            }
        }
    }
}

// ---------------- #7: final output (block 0) + scratch cleanup (blocks 1..) ----------------
__global__ void k_out(float* __restrict__ out, const float* __restrict__ fcb,
                      const int* __restrict__ batch) {
    if (blockIdx.x == 0) {
        int g = threadIdx.x;
        if (g >= N_GRAPHS) return;
        int lo = 0, hi = N_NODES;
        while (lo < hi) { int m = (lo + hi) >> 1; if (batch[m] < g) lo = m + 1; else hi = m; }
        int lo2 = lo, hi2 = N_NODES;
        while (lo2 < hi2) { int m = (lo2 + hi2) >> 1; if (batch[m] < g + 1) lo2 = m + 1; else hi2 = m; }
        float c = (float)(lo2 - lo);
        out[g] = g_gsum[g] / fmaxf(c, 1.f) + fcb[0];
    } else {
        int i = (blockIdx.x - 1) * 256 + threadIdx.x;
        if (i < N_NODES) { g_deg[i] = 0; g_sattr[i] = 0.f; }
    }
}

// ---------------- launch ----------------
extern "C" void kernel_launch(void* const* d_in, const int* in_sizes, int n_in,
                              void* d_out, int out_size) {
    const float* x    = (const float*)d_in[0];
    const float* ea   = (const float*)d_in[1];
    const float* ew   = (const float*)d_in[2];
    const float* eb   = (const float*)d_in[3];
    const float* nw   = (const float*)d_in[4];
    const float* nb   = (const float*)d_in[5];
    const float* fcw  = (const float*)d_in[6];
    const float* fcb  = (const float*)d_in[7];
    const int*   ei   = (const int*)d_in[8];
    const int*   batch= (const int*)d_in[9];
    float* out = (float*)d_out;

    __half* xh; cudaGetSymbolAddress((void**)&xh, g_xh);
    __half* h0; cudaGetSymbolAddress((void**)&h0, g_h0);
    __half* h1; cudaGetSymbolAddress((void**)&h1, g_h1);

    k_pre  <<<EB4 + CVB, 256>>>(ei, ea, x);        // #1
    k_scan1<<<NB_NODES + 1, 256>>>(ew, eb, nw);    // #2
    k_edge2<<<EB4, 256>>>(ei);                     // #3

    const int LB = 592;                            // 4 blocks/SM, work-stealing
    k_layer<<<LB, 256>>>(xh, h0, nw, nb, 0, 0, fcw, batch);   // #4 -> profiled
    k_layer<<<LB, 256>>>(h0, h1, nw, nb, 1, 0, fcw, batch);   // #5
    k_layer<<<LB, 256>>>(h1, h0, nw, nb, 2, 1, fcw, batch);   // #6 fused pooling

    k_out<<<NB_NODES + 1, 256>>>(out, fcb, batch); // #7 output + cleanup
}

// round 14
// speedup vs baseline: 1.3776x; 1.1325x over previous
#include <cuda_runtime.h>
#include <cuda_fp16.h>

#define N_NODES 50000
#define N_EDGES 800000
#define HID 64
#define N_LAYERS 3
#define N_GRAPHS 64
#define NB_NODES 196        // ceil(50000/256)
#define EB4 782             // ceil(800000/4/256)
#define CVB 6250            // N_NODES*32 float2 / 256
#define PERM_SZ (N_EDGES + 3 * N_NODES)
#define FULL 0xffffffffu
#define AST 72              // A/W tile row stride in halves (144B: 16B-aligned, conflict-free)

// ---------------- scratch (device globals; zero-initialized at module load) ----------------
// feature buffers have one extra all-zero row (index N_NODES) used as gather padding.
__device__ __half g_xh[(N_NODES + 1) * HID];
__device__ __half g_h0[(N_NODES + 1) * HID];
__device__ __half g_h1[(N_NODES + 1) * HID];
__device__ int    g_deg[N_NODES];        // zero at entry (k_out restores)
__device__ int    g_rowptr[N_NODES];     // padded CSR offsets (multiples of 4)
__device__ int    g_fill[N_NODES];
__device__ __align__(16) int g_perm[PERM_SZ];
__device__ float  g_sattr[N_NODES];      // zero at entry (k_out restores)
__device__ float  g_c1[N_LAYERS][HID];
__device__ float  g_c2[N_LAYERS][HID];
__device__ float  g_gsum[N_GRAPHS];      // zeroed in k_scan1
__device__ int    g_ctr[N_LAYERS];       // work-steal counters, zeroed in k_scan1

// ---------------- #1: edge pass 1 (deg + sattr, 4 edges/thread) + fp16 convert ----------------
__global__ void k_pre(const int* __restrict__ ei, const float* __restrict__ ea,
                      const float* __restrict__ x) {
    if (blockIdx.x < EB4) {
        int p = blockIdx.x * 256 + threadIdx.x;
        int e = p * 4;
        if (e >= N_EDGES) return;
        int4   d4 = *(const int4*)  (ei + N_EDGES + e);
        float4 a4 = *(const float4*)(ea + e);
        atomicAdd(&g_deg[d4.x], 1);  atomicAdd(&g_sattr[d4.x], a4.x);
        atomicAdd(&g_deg[d4.y], 1);  atomicAdd(&g_sattr[d4.y], a4.y);
        atomicAdd(&g_deg[d4.z], 1);  atomicAdd(&g_sattr[d4.z], a4.z);
        atomicAdd(&g_deg[d4.w], 1);  atomicAdd(&g_sattr[d4.w], a4.w);
    } else {
        int i = (blockIdx.x - EB4) * 256 + threadIdx.x;   // float2 index
        if (i < N_NODES * 32) {
            float2 v = ((const float2*)x)[i];
            ((__half2*)g_xh)[i] = __floats2half2_rn(v.x, v.y);
        }
    }
}

// ---------------- #2: scan over PADDED degrees + pad-slot fill + constants ----------------
__global__ void __launch_bounds__(256) k_scan1(const float* __restrict__ ew,
                                               const float* __restrict__ eb,
                                               const float* __restrict__ nw) {
    const int b = blockIdx.x, tid = threadIdx.x;
    if (b == NB_NODES) {
        if (tid < N_GRAPHS) g_gsum[tid] = 0.f;
        if (tid < N_LAYERS) g_ctr[tid] = 0;
        if (tid >= N_LAYERS * HID) return;
        int l = tid / HID, h = tid % HID;
        float a = 0.f, c = 0.f;
        for (int k = 0; k < HID; k++) {
            float w = nw[(l * 2 * HID + HID + k) * HID + h];  // W2[k][h]
            a += ew[l * HID + k] * w;
            c += eb[l * HID + k] * w;
        }
        g_c1[l][h] = a;
        g_c2[l][h] = c;
        return;
    }

    __shared__ int sW[8];
    __shared__ int sBase;
    const int lane = tid & 31, w = tid >> 5;

    const int4* __restrict__ d4 = (const int4*)g_deg;
    const int nq = b * 64;
    int s = 0;
    for (int j = tid; j < nq; j += 256) {
        int4 v = d4[j];
        s += ((v.x + 3) & ~3) + ((v.y + 3) & ~3) + ((v.z + 3) & ~3) + ((v.w + 3) & ~3);
    }
#pragma unroll
    for (int o = 16; o; o >>= 1) s += __shfl_down_sync(FULL, s, o);
    if (lane == 0) sW[w] = s;
    __syncthreads();
    if (tid == 0) {
        int t = 0;
#pragma unroll
        for (int j = 0; j < 8; j++) t += sW[j];
        sBase = t;
    }
    __syncthreads();
    const int base = sBase;
    __syncthreads();

    int i = b * 256 + tid;
    int v = (i < N_NODES) ? g_deg[i] : 0;
    int pv = (v + 3) & ~3;
    int inc = pv;
#pragma unroll
    for (int o = 1; o < 32; o <<= 1) {
        int t = __shfl_up_sync(FULL, inc, o);
        if (lane >= o) inc += t;
    }
    if (lane == 31) sW[w] = inc;
    __syncthreads();
    int wo = 0;
    for (int j = 0; j < w; j++) wo += sW[j];
    int exc = base + wo + inc - pv;
    if (i < N_NODES) {
        g_rowptr[i] = exc;
        g_fill[i] = exc;
        for (int t = v; t < pv; t++) g_perm[exc + t] = N_NODES;  // pad -> zero row
    }
}

// ---------------- #3: edge pass 2: CSR bucket placement (4 edges/thread) ----------------
__global__ void k_edge2(const int* __restrict__ ei) {
    int p = blockIdx.x * blockDim.x + threadIdx.x;
    int e = p * 4;
    if (e >= N_EDGES) return;
    int4 s4 = *(const int4*)(ei + e);
    int4 d4 = *(const int4*)(ei + N_EDGES + e);
    g_perm[atomicAdd(&g_fill[d4.x], 1)] = s4.x;
    g_perm[atomicAdd(&g_fill[d4.y], 1)] = s4.y;
    g_perm[atomicAdd(&g_fill[d4.z], 1)] = s4.z;
    g_perm[atomicAdd(&g_fill[d4.w], 1)] = s4.w;
}

// ---------------- #4-6: fused layer: HADD2 gather -> HMMA (mma.sync) MLP ----------------
__global__ void __launch_bounds__(256, 4) k_layer(
    const __half* __restrict__ xin, __half* __restrict__ xout,
    const float* __restrict__ nw, const float* __restrict__ nb, int l,
    int last, const float* __restrict__ fcw, const int* __restrict__ batch)
{
    __shared__ __half sWh[HID * AST];       // Wt[h][k] fp16, stride 72 halves   9.2KB
    __shared__ __half sAh[8 * 16 * AST];    // per-warp A tile 16x64 (rows 8-15 zero) 18.4KB
    __shared__ float  sC[4][HID];           // c1, c2, bias, fcw                 1KB
    const int tid = threadIdx.x;

    {   // stage W1 transposed fp16 + zero A tiles + stage constants
        const float* __restrict__ nwl = nw + (size_t)l * 2 * HID * HID;
        for (int i = tid; i < HID * HID; i += 256) {
            int h = i & 63, k = i >> 6;
            sWh[h * AST + k] = __float2half(nwl[k * HID + h]);
        }
        for (int i = tid; i < 8 * 16 * AST / 2; i += 256)
            ((unsigned*)sAh)[i] = 0u;
        if (tid < HID) {
            sC[0][tid] = g_c1[l][tid];
            sC[1][tid] = g_c2[l][tid];
            sC[2][tid] = nb[l * HID + tid];
            sC[3][tid] = fcw[tid];
        }
    }
    __syncthreads();

    const int warp = tid >> 5, lane = tid & 31;
    const int q = lane >> 3, c = lane & 7;   // quarter-warp id, col-block
    __half* __restrict__ sAw = sAh + warp * 16 * AST;
    const unsigned sA_base = (unsigned)__cvta_generic_to_shared(sAw);
    const unsigned sW_base = (unsigned)__cvta_generic_to_shared(sWh);
    const uint4* __restrict__ xh4 = (const uint4*)xin;   // 8 halves per lane

    for (;;) {
        int base;
        if (lane == 0) base = atomicAdd(&g_ctr[l], 8);
        base = __shfl_sync(FULL, base, 0);
        if (base >= N_NODES) break;

        int bp = 0, dp = 0;
        if (lane < 8) {                      // base+lane always < N_NODES (50000 % 8 == 0)
            bp = g_rowptr[base + lane];
            dp = g_deg[base + lane];
        }

        // ---- gather: each quarter-warp owns nodes base+q and base+q+4 ----
#pragma unroll
        for (int half = 0; half < 2; half++) {
            const int slot = q + 4 * half;
            const int bj = __shfl_sync(FULL, bp, slot);
            const int pd = (__shfl_sync(FULL, dp, slot) + 3) & ~3;

            __half2 z = __floats2half2_rn(0.f, 0.f);
            __half2 A0[4] = {z, z, z, z};
            __half2 A1[4] = {z, z, z, z};
            __half2 A2[4] = {z, z, z, z};
            __half2 A3[4] = {z, z, z, z};
            const int4* __restrict__ pB4 = (const int4*)(g_perm + bj);  // 16B aligned
#pragma unroll 2
            for (int i = 0; i < (pd >> 2); i++) {
                const int4 s4 = pB4[i];                 // one LDG.128: 4 indices
                const uint4 v0 = xh4[s4.x * 8 + c];
                const uint4 v1 = xh4[s4.y * 8 + c];
                const uint4 v2 = xh4[s4.z * 8 + c];
                const uint4 v3 = xh4[s4.w * 8 + c];
                A0[0] = __hadd2(A0[0], *(const __half2*)&v0.x);
                A0[1] = __hadd2(A0[1], *(const __half2*)&v0.y);
                A0[2] = __hadd2(A0[2], *(const __half2*)&v0.z);
                A0[3] = __hadd2(A0[3], *(const __half2*)&v0.w);
                A1[0] = __hadd2(A1[0], *(const __half2*)&v1.x);
                A1[1] = __hadd2(A1[1], *(const __half2*)&v1.y);
                A1[2] = __hadd2(A1[2], *(const __half2*)&v1.z);
                A1[3] = __hadd2(A1[3], *(const __half2*)&v1.w);
                A2[0] = __hadd2(A2[0], *(const __half2*)&v2.x);
                A2[1] = __hadd2(A2[1], *(const __half2*)&v2.y);
                A2[2] = __hadd2(A2[2], *(const __half2*)&v2.z);
                A2[3] = __hadd2(A2[3], *(const __half2*)&v2.w);
                A3[0] = __hadd2(A3[0], *(const __half2*)&v3.x);
                A3[1] = __hadd2(A3[1], *(const __half2*)&v3.y);
                A3[2] = __hadd2(A3[2], *(const __half2*)&v3.z);
                A3[3] = __hadd2(A3[3], *(const __half2*)&v3.w);
            }
            __half2 m0 = __hadd2(__hadd2(A0[0], A1[0]), __hadd2(A2[0], A3[0]));
            __half2 m1 = __hadd2(__hadd2(A0[1], A1[1]), __hadd2(A2[1], A3[1]));
            __half2 m2 = __hadd2(__hadd2(A0[2], A1[2]), __hadd2(A2[2], A3[2]));
            __half2 m3 = __hadd2(__hadd2(A0[3], A1[3]), __hadd2(A2[3], A3[3]));
            uint4 o;
            o.x = *(unsigned*)&m0;  o.y = *(unsigned*)&m1;
            o.z = *(unsigned*)&m2;  o.w = *(unsigned*)&m3;
            *(uint4*)&sAw[slot * AST + 8 * c] = o;      // fp16 row, STS.128
        }
        __syncwarp();

        // ---- MLP: mma.sync m16n8k16 (rows 8-15 of A permanently zero) ----
        float d[8][4];
#pragma unroll
        for (int nt = 0; nt < 8; nt++) {
            d[nt][0] = 0.f; d[nt][1] = 0.f; d[nt][2] = 0.f; d[nt][3] = 0.f;
        }
        const int t = lane >> 3, rr = lane & 7;
#pragma unroll
        for (int kt = 0; kt < 4; kt++) {
            unsigned a0, a1, a2, a3;
            {
                const unsigned addrA = sA_base +
                    (((rr + ((t & 1) << 3)) * AST + kt * 16 + ((t >> 1) << 3)) << 1);
                asm volatile("ldmatrix.sync.aligned.m8n8.x4.shared.b16 {%0,%1,%2,%3}, [%4];"
                    : "=r"(a0), "=r"(a1), "=r"(a2), "=r"(a3) : "r"(addrA));
            }
#pragma unroll
            for (int p = 0; p < 4; p++) {
                unsigned b0, b1, b2, b3;
                const unsigned addrB = sW_base +
                    ((((2 * p + (t >> 1)) * 8 + rr) * AST + kt * 16 + ((t & 1) << 3)) << 1);
                asm volatile("ldmatrix.sync.aligned.m8n8.x4.shared.b16 {%0,%1,%2,%3}, [%4];"
                    : "=r"(b0), "=r"(b1), "=r"(b2), "=r"(b3) : "r"(addrB));
                asm volatile("mma.sync.aligned.m16n8k16.row.col.f32.f16.f16.f32 "
                    "{%0,%1,%2,%3}, {%4,%5,%6,%7}, {%8,%9}, {%0,%1,%2,%3};"
                    : "+f"(d[2*p][0]), "+f"(d[2*p][1]), "+f"(d[2*p][2]), "+f"(d[2*p][3])
                    : "r"(a0), "r"(a1), "r"(a2), "r"(a3), "r"(b0), "r"(b1));
                asm volatile("mma.sync.aligned.m16n8k16.row.col.f32.f16.f16.f32 "
                    "{%0,%1,%2,%3}, {%4,%5,%6,%7}, {%8,%9}, {%0,%1,%2,%3};"
                    : "+f"(d[2*p+1][0]), "+f"(d[2*p+1][1]), "+f"(d[2*p+1][2]), "+f"(d[2*p+1][3])
                    : "r"(a0), "r"(a1), "r"(a2), "r"(a3), "r"(b2), "r"(b3));
            }
        }

        // ---- epilogue: lane owns node base+(lane>>2), cols nt*8 + 2*(lane&3)+{0,1} ----
        {
            const int r = lane >> 2;
            const int node = base + r;
            const float sa = g_sattr[node];
            const float dg = (float)__shfl_sync(FULL, dp, r);
            const int cb = 2 * (lane & 3);
            if (!last) {
#pragma unroll
                for (int nt = 0; nt < 8; nt++) {
                    const int c0 = nt * 8 + cb;
                    const float2 c1v = *(const float2*)&sC[0][c0];
                    const float2 c2v = *(const float2*)&sC[1][c0];
                    const float2 bv  = *(const float2*)&sC[2][c0];
                    float u0 = d[nt][0] + sa * c1v.x + dg * c2v.x + bv.x;
                    float u1 = d[nt][1] + sa * c1v.y + dg * c2v.y + bv.y;
                    u0 = fmaxf(u0, 0.f);   // ReLU; LeakyReLU identity on >= 0
                    u1 = fmaxf(u1, 0.f);
                    ((__half2*)xout)[node * 32 + (c0 >> 1)] = __floats2half2_rn(u0, u1);
                }
            } else {
                float s = 0.f;
#pragma unroll
                for (int nt = 0; nt < 8; nt++) {
                    const int c0 = nt * 8 + cb;
                    const float2 c1v = *(const float2*)&sC[0][c0];
                    const float2 c2v = *(const float2*)&sC[1][c0];
                    const float2 bv  = *(const float2*)&sC[2][c0];
                    const float2 fv  = *(const float2*)&sC[3][c0];
                    float u0 = d[nt][0] + sa * c1v.x + dg * c2v.x + bv.x;
                    float u1 = d[nt][1] + sa * c1v.y + dg * c2v.y + bv.y;
                    u0 = fmaxf(u0, 0.f);
                    u1 = fmaxf(u1, 0.f);
                    s += u0 * fv.x + u1 * fv.y;
                }
                s += __shfl_xor_sync(FULL, s, 1);
                s += __shfl_xor_sync(FULL, s, 2);
                if ((lane & 3) == 0) atomicAdd(&g_gsum[batch[node]], s);
            }
        }
    }
}

// ---------------- #7: final output (block 0) + scratch cleanup (blocks 1..) ----------------
__global__ void k_out(float* __restrict__ out, const float* __restrict__ fcb,
                      const int* __restrict__ batch) {
    if (blockIdx.x == 0) {
        int g = threadIdx.x;
        if (g >= N_GRAPHS) return;
        int lo = 0, hi = N_NODES;
        while (lo < hi) { int m = (lo + hi) >> 1; if (batch[m] < g) lo = m + 1; else hi = m; }
        int lo2 = lo, hi2 = N_NODES;
        while (lo2 < hi2) { int m = (lo2 + hi2) >> 1; if (batch[m] < g + 1) lo2 = m + 1; else hi2 = m; }
        float c = (float)(lo2 - lo);
        out[g] = g_gsum[g] / fmaxf(c, 1.f) + fcb[0];
    } else {
        int i = (blockIdx.x - 1) * 256 + threadIdx.x;
        if (i < N_NODES) { g_deg[i] = 0; g_sattr[i] = 0.f; }
    }
}

// ---------------- launch ----------------
extern "C" void kernel_launch(void* const* d_in, const int* in_sizes, int n_in,
                              void* d_out, int out_size) {
    const float* x    = (const float*)d_in[0];
    const float* ea   = (const float*)d_in[1];
    const float* ew   = (const float*)d_in[2];
    const float* eb   = (const float*)d_in[3];
    const float* nw   = (const float*)d_in[4];
    const float* nb   = (const float*)d_in[5];
    const float* fcw  = (const float*)d_in[6];
    const float* fcb  = (const float*)d_in[7];
    const int*   ei   = (const int*)d_in[8];
    const int*   batch= (const int*)d_in[9];
    float* out = (float*)d_out;

    __half* xh; cudaGetSymbolAddress((void**)&xh, g_xh);
    __half* h0; cudaGetSymbolAddress((void**)&h0, g_h0);
    __half* h1; cudaGetSymbolAddress((void**)&h1, g_h1);

    k_pre  <<<EB4 + CVB, 256>>>(ei, ea, x);        // #1
    k_scan1<<<NB_NODES + 1, 256>>>(ew, eb, nw);    // #2
    k_edge2<<<EB4, 256>>>(ei);                     // #3

    const int LB = 592;                            // 4 blocks/SM, work-stealing
    k_layer<<<LB, 256>>>(xh, h0, nw, nb, 0, 0, fcw, batch);   // #4 -> profiled
    k_layer<<<LB, 256>>>(h0, h1, nw, nb, 1, 0, fcw, batch);   // #5
    k_layer<<<LB, 256>>>(h1, h0, nw, nb, 2, 1, fcw, batch);   // #6 fused pooling

    k_out<<<NB_NODES + 1, 256>>>(out, fcb, batch); // #7 output + cleanup
}